// round 9
// baseline (speedup 1.0000x reference)
#include <cuda_runtime.h>
#include <math.h>

// Problem constants
#define B  32
#define C  200
#define H  56
#define W  56
#define HW 3136
#define OH 224
#define OW 224
#define KS 33
#define PAD 16

#define MSP2 68         // 64x64 chunk pitch (floats); 272B rows, 16B aligned

// Scratch (device globals) — g_delta layout: [hw][c][b]
__device__ float g_delta[(size_t)HW * C * B];
__device__ float g_dist[(size_t)B * HW];
__device__ float g_up[(size_t)B * OH * OW];
__device__ float g_tmp[(size_t)B * OH * OW];
__device__ float g_gw[KS];

// ---------------- packed f32x2 helpers ----------------
__device__ __forceinline__ unsigned long long fma2(unsigned long long a,
                                                   unsigned long long b,
                                                   unsigned long long c)
{
    unsigned long long d;
    asm("fma.rn.f32x2 %0, %1, %2, %3;" : "=l"(d) : "l"(a), "l"(b), "l"(c));
    return d;
}
__device__ __forceinline__ unsigned long long pack2(float x)
{
    unsigned long long d;
    asm("mov.b64 %0, {%1, %1};" : "=l"(d) : "f"(x));
    return d;
}
__device__ __forceinline__ float2 unpack2(unsigned long long v)
{
    float2 r;
    asm("mov.b64 {%0, %1}, %2;" : "=f"(r.x), "=f"(r.y) : "l"(v));
    return r;
}

// ---------------------------------------------------------------------------
// Kernel 1: delta transpose prepass: emb[b][c][hw] -> g_delta[hw][c][b]
// ---------------------------------------------------------------------------
__global__ void prep_delta_kernel(const float* __restrict__ emb,
                                  const float* __restrict__ mean)
{
    __shared__ float s[8][32][33];
    const int hw0 = blockIdx.x * 32;
    const int c0  = blockIdx.y * 8;
    const int lane = threadIdx.x & 31;
    const int wrp  = threadIdx.x >> 5;

    const int c = c0 + wrp;
    const float m = mean[(size_t)c * HW + hw0 + lane];
    #pragma unroll 4
    for (int b = 0; b < B; b++) {
        float e = emb[((size_t)b * C + c) * HW + hw0 + lane];
        s[wrp][b][lane] = e - m;
    }
    __syncthreads();

    const int b  = threadIdx.x & 31;
    const int cl = threadIdx.x >> 5;
    #pragma unroll 4
    for (int hwl = 0; hwl < 32; hwl++) {
        g_delta[(size_t)(hw0 + hwl) * (C * B) + (c0 + cl) * B + b] = s[cl][b][hwl];
    }
}

// ---------------------------------------------------------------------------
// Kernel 2: per-pixel mahalanobis, symmetric 64x64 schedule.
// Geometry: 128 thr = 4 jg x 8 ty x 4 tx. Each thread: 8 rows (ty+8r) x
// 8 batches (tx*8..) over a 16-column j-subrange (jg). Partial row-sums
// fold independently per jg; final cross-group reduction sums them.
// Chunk smem traffic: 16KB*4 (M) + 8KB*8 (D) = 128 KB.
// ---------------------------------------------------------------------------
__global__ void __launch_bounds__(128)
mahal_kernel(const float* __restrict__ invcov)
{
    extern __shared__ float sm[];
    float* Ds  = sm;                      // 6400 floats [j][b]
    float* Mb0 = sm + C * B;              // 64*68
    float* Mb1 = Mb0 + 64 * MSP2;         // 64*68 (also border staging)

    const int p   = blockIdx.x;
    const int tid = threadIdx.x;
    const int tx  = tid & 3;              // 0..3  -> 8 batches
    const int g   = tid >> 2;             // 0..31 (group = jg*8 + ty)
    const int ty  = g & 7;                // 0..7
    const int jg  = g >> 3;               // 0..3
    const int b0  = tx * 8;

    const float* Mp = invcov + (size_t)p * (C * C);

    // chunk schedule: (I,J,weight); 64-blocks, J <= I
    const int   CI[6] = {0, 1, 1, 2, 2, 2};
    const int   CJ[6] = {0, 0, 1, 0, 1, 2};
    const float CW[6] = {1.f, 2.f, 1.f, 2.f, 2.f, 1.f};

    // ---- issue chunk 0 LDGs first (1024 float4 / 128 thr = 8 each) ----
    float4 st[8];
    #pragma unroll
    for (int o = 0; o < 8; o++) {
        int e4 = o * 128 + tid;
        int il = e4 >> 4;
        int jl = (e4 & 15) * 4;
        st[o] = *(const float4*)&Mp[(size_t)il * C + jl];
    }

    // ---- stage delta (coalesced) ----
    const float* dsrc = g_delta + (size_t)p * (C * B);
    #pragma unroll
    for (int i = tid * 4; i < C * B; i += 512)
        *(float4*)&Ds[i] = *(const float4*)&dsrc[i];

    // ---- stage border rows 192..199 (8 x 200) into Mb1 ----
    #pragma unroll
    for (int i = tid * 4; i < 8 * C; i += 512)
        *(float4*)&Mb1[i] = *(const float4*)&Mp[(size_t)192 * C + i];

    __syncthreads();

    float q0 = 0.f, q1 = 0.f, q2 = 0.f, q3 = 0.f;
    float q4 = 0.f, q5 = 0.f, q6 = 0.f, q7 = 0.f;

    // ---- border strip: rows 192..199, col-weight 2 (j<192) / 1 ----
    #pragma unroll
    for (int rr = 0; rr < 8; rr++) {
        const float* mrow = &Mb1[rr * C];
        float p0 = 0.f, p1 = 0.f, p2 = 0.f, p3 = 0.f;
        float p4 = 0.f, p5 = 0.f, p6 = 0.f, p7 = 0.f;
        #pragma unroll
        for (int s = 0; s < 6; s++) {             // j = g + 32s < 192
            int j = g + 32 * s;
            float wm = 2.f * mrow[j];
            float4 dj0 = *(const float4*)&Ds[j * B + b0];
            float4 dj1 = *(const float4*)&Ds[j * B + b0 + 4];
            p0 += wm * dj0.x; p1 += wm * dj0.y; p2 += wm * dj0.z; p3 += wm * dj0.w;
            p4 += wm * dj1.x; p5 += wm * dj1.y; p6 += wm * dj1.z; p7 += wm * dj1.w;
        }
        if (g < 8) {                               // j = 192 + g, weight 1
            int j = 192 + g;
            float wm = mrow[j];
            float4 dj0 = *(const float4*)&Ds[j * B + b0];
            float4 dj1 = *(const float4*)&Ds[j * B + b0 + 4];
            p0 += wm * dj0.x; p1 += wm * dj0.y; p2 += wm * dj0.z; p3 += wm * dj0.w;
            p4 += wm * dj1.x; p5 += wm * dj1.y; p6 += wm * dj1.z; p7 += wm * dj1.w;
        }
        float4 di0 = *(const float4*)&Ds[(192 + rr) * B + b0];
        float4 di1 = *(const float4*)&Ds[(192 + rr) * B + b0 + 4];
        q0 += di0.x * p0; q1 += di0.y * p1; q2 += di0.z * p2; q3 += di0.w * p3;
        q4 += di1.x * p4; q5 += di1.y * p5; q6 += di1.z * p6; q7 += di1.w * p7;
    }

    // ---- 6-chunk pipeline over 64x64 blocks, register-staged double buffer ----
    #pragma unroll
    for (int k = 0; k < 6; k++) {
        float* buf = (k & 1) ? Mb1 : Mb0;
        __syncthreads();                       // prior readers of buf done
        #pragma unroll
        for (int o = 0; o < 8; o++) {
            int e4 = o * 128 + tid;
            int il = e4 >> 4;
            int jl = (e4 & 15) * 4;
            *(float4*)&buf[il * MSP2 + jl] = st[o];
        }
        __syncthreads();

        if (k < 5) {                           // prefetch next chunk
            const float* src = Mp + (size_t)(64 * CI[k + 1]) * C + 64 * CJ[k + 1];
            #pragma unroll
            for (int o = 0; o < 8; o++) {
                int e4 = o * 128 + tid;
                int il = e4 >> 4;
                int jl = (e4 & 15) * 4;
                st[o] = *(const float4*)&src[(size_t)il * C + jl];
            }
        }

        // ---- compute chunk k: 8 rows x 8 batches over 16-col subrange ----
        unsigned long long acc[8][4];
        #pragma unroll
        for (int r = 0; r < 8; r++)
            #pragma unroll
            for (int w = 0; w < 4; w++) acc[r][w] = 0ull;

        const float* dbase = &Ds[(64 * CJ[k] + jg * 16) * B + b0];
        const int mcol = jg * 16;
        #pragma unroll
        for (int u = 0; u < 4; u++) {
            float4 mv[8];
            #pragma unroll
            for (int r = 0; r < 8; r++)
                mv[r] = *(const float4*)&buf[(ty + 8 * r) * MSP2 + mcol + u * 4];
            #pragma unroll
            for (int jj = 0; jj < 4; jj++) {
                const float* dp = dbase + (u * 4 + jj) * B;
                ulonglong2 dA = *(const ulonglong2*)(dp);        // b0..b0+3
                ulonglong2 dB = *(const ulonglong2*)(dp + 4);    // b0+4..b0+7
                #pragma unroll
                for (int r = 0; r < 8; r++) {
                    float c = (jj == 0) ? mv[r].x : (jj == 1) ? mv[r].y
                            : (jj == 2) ? mv[r].z : mv[r].w;
                    unsigned long long m = pack2(c);
                    acc[r][0] = fma2(m, dA.x, acc[r][0]);
                    acc[r][1] = fma2(m, dA.y, acc[r][1]);
                    acc[r][2] = fma2(m, dB.x, acc[r][2]);
                    acc[r][3] = fma2(m, dB.y, acc[r][3]);
                }
            }
        }

        // ---- fold with weight (partial over this jg's columns) ----
        {
            const float w = CW[k];
            #pragma unroll
            for (int r = 0; r < 8; r++) {
                int i = 64 * CI[k] + ty + 8 * r;
                float4 dv0 = *(const float4*)&Ds[i * B + b0];
                float4 dv1 = *(const float4*)&Ds[i * B + b0 + 4];
                float2 s0 = unpack2(acc[r][0]);
                float2 s1 = unpack2(acc[r][1]);
                float2 s2 = unpack2(acc[r][2]);
                float2 s3 = unpack2(acc[r][3]);
                q0 += w * dv0.x * s0.x;
                q1 += w * dv0.y * s0.y;
                q2 += w * dv0.z * s1.x;
                q3 += w * dv0.w * s1.y;
                q4 += w * dv1.x * s2.x;
                q5 += w * dv1.y * s2.y;
                q6 += w * dv1.z * s3.x;
                q7 += w * dv1.w * s3.y;
            }
        }
    }

    // ---- block reduction over 32 groups per b ----
    __syncthreads();
    float* red = Mb0;                   // 32*33 floats scratch
    red[g * 33 + b0 + 0] = q0;
    red[g * 33 + b0 + 1] = q1;
    red[g * 33 + b0 + 2] = q2;
    red[g * 33 + b0 + 3] = q3;
    red[g * 33 + b0 + 4] = q4;
    red[g * 33 + b0 + 5] = q5;
    red[g * 33 + b0 + 6] = q6;
    red[g * 33 + b0 + 7] = q7;
    __syncthreads();
    if (tid < B) {
        float acc = 0.f;
        #pragma unroll
        for (int t = 0; t < 32; t++) acc += red[t * 33 + tid];
        g_dist[(size_t)tid * HW + p] = sqrtf(fmaxf(acc, 0.f));
    }
}

// ---------------------------------------------------------------------------
// Kernel 3: gaussian weight init
// ---------------------------------------------------------------------------
__global__ void gauss_init_kernel()
{
    if (threadIdx.x == 0 && blockIdx.x == 0) {
        float w[KS];
        float s = 0.f;
        for (int i = 0; i < KS; i++) {
            float x = (float)(i - (KS - 1) / 2);
            w[i] = expf(-(x * x) / (2.f * 16.f));
            s += w[i];
        }
        for (int i = 0; i < KS; i++) g_gw[i] = w[i] / s;
    }
}

// ---------------------------------------------------------------------------
// Kernel 4: bilinear upsample 56x56 -> 224x224
// ---------------------------------------------------------------------------
__global__ void upsample_kernel()
{
    int idx = blockIdx.x * 256 + threadIdx.x;
    const int total = B * OH * OW;
    if (idx >= total) return;
    int x = idx % OW;
    int y = (idx / OW) % OH;
    int b = idx / (OW * OH);

    float sy = y * 0.25f - 0.375f;
    float sx = x * 0.25f - 0.375f;
    float fy0 = floorf(sy), fx0 = floorf(sx);
    float ay = sy - fy0, ax = sx - fx0;
    int y0 = (int)fy0, x0 = (int)fx0;
    int y1 = min(y0 + 1, H - 1);
    int x1 = min(x0 + 1, W - 1);
    y0 = max(y0, 0);
    x0 = max(x0, 0);

    const float* src = g_dist + (size_t)b * HW;
    float v00 = src[y0 * W + x0];
    float v01 = src[y0 * W + x1];
    float v10 = src[y1 * W + x0];
    float v11 = src[y1 * W + x1];
    float top = v00 + ax * (v01 - v00);
    float bot = v10 + ax * (v11 - v10);
    g_up[idx] = top + ay * (bot - top);
}

// ---------------------------------------------------------------------------
// Kernels 5/6: separable gaussian blur, reflect padding
// ---------------------------------------------------------------------------
__device__ __forceinline__ int reflect224(int i)
{
    if (i < 0) i = -i;
    if (i > OW - 1) i = 2 * (OW - 1) - i;
    return i;
}

__global__ void blur_h_kernel()
{
    __shared__ float sgw[KS];
    if (threadIdx.x < KS) sgw[threadIdx.x] = g_gw[threadIdx.x];
    __syncthreads();

    int idx = blockIdx.x * 256 + threadIdx.x;
    const int total = B * OH * OW;
    if (idx >= total) return;
    int x = idx % OW;
    int row_base = idx - x;

    float acc = 0.f;
    #pragma unroll
    for (int t = 0; t < KS; t++) {
        int xs = reflect224(x + t - PAD);
        acc += sgw[t] * g_up[row_base + xs];
    }
    g_tmp[idx] = acc;
}

__global__ void blur_v_kernel(float* __restrict__ out)
{
    __shared__ float sgw[KS];
    if (threadIdx.x < KS) sgw[threadIdx.x] = g_gw[threadIdx.x];
    __syncthreads();

    int idx = blockIdx.x * 256 + threadIdx.x;
    const int total = B * OH * OW;
    if (idx >= total) return;
    int x = idx % OW;
    int y = (idx / OW) % OH;
    int b = idx / (OW * OH);
    const float* src = g_tmp + (size_t)b * OH * OW;

    float acc = 0.f;
    #pragma unroll
    for (int t = 0; t < KS; t++) {
        int ys = reflect224(y + t - PAD);
        acc += sgw[t] * src[ys * OW + x];
    }
    out[idx] = acc;
}

// ---------------------------------------------------------------------------
// Launch
// ---------------------------------------------------------------------------
extern "C" void kernel_launch(void* const* d_in, const int* in_sizes, int n_in,
                              void* d_out, int out_size)
{
    const float* emb    = (const float*)d_in[0];
    const float* mean   = (const float*)d_in[1];
    const float* invcov = (const float*)d_in[2];
    float* out = (float*)d_out;

    const int mahal_smem = (C * B + 2 * 64 * MSP2) * (int)sizeof(float);  // 60416
    cudaFuncSetAttribute(mahal_kernel,
                         cudaFuncAttributeMaxDynamicSharedMemorySize, mahal_smem);

    dim3 prep_grid(HW / 32, C / 8);
    prep_delta_kernel<<<prep_grid, 256>>>(emb, mean);

    mahal_kernel<<<HW, 128, mahal_smem>>>(invcov);

    gauss_init_kernel<<<1, 32>>>();

    const int total = B * OH * OW;
    const int nb = (total + 255) / 256;
    upsample_kernel<<<nb, 256>>>();
    blur_h_kernel<<<nb, 256>>>();
    blur_v_kernel<<<nb, 256>>>(out);
}

// round 10
// speedup vs baseline: 1.0448x; 1.0448x over previous
#include <cuda_runtime.h>
#include <math.h>

// Problem constants
#define B  32
#define C  200
#define H  56
#define W  56
#define HW 3136
#define OH 224
#define OW 224
#define KS 33

#define MSP2 68         // 64x64 chunk pitch (floats); 272B rows, 16B aligned

// Scratch (device globals) — g_delta layout: [hw][c][b]
__device__ float g_delta[(size_t)HW * C * B];
__device__ float g_dist[(size_t)B * HW];          // [b][hw]
__device__ float g_tmp[(size_t)B * 56 * OW];      // [b][y56][x224]
__device__ float g_K[OH * 56];                    // combined blur*upsample [y][s]
__device__ float g_KT[56 * OH];                   // transposed [s][y]

// ---------------- packed f32x2 helpers ----------------
__device__ __forceinline__ unsigned long long fma2(unsigned long long a,
                                                   unsigned long long b,
                                                   unsigned long long c)
{
    unsigned long long d;
    asm("fma.rn.f32x2 %0, %1, %2, %3;" : "=l"(d) : "l"(a), "l"(b), "l"(c));
    return d;
}
__device__ __forceinline__ unsigned long long pack2(float x)
{
    unsigned long long d;
    asm("mov.b64 %0, {%1, %1};" : "=l"(d) : "f"(x));
    return d;
}
__device__ __forceinline__ float2 unpack2(unsigned long long v)
{
    float2 r;
    asm("mov.b64 {%0, %1}, %2;" : "=f"(r.x), "=f"(r.y) : "l"(v));
    return r;
}

// ---------------------------------------------------------------------------
// Kernel 1: delta transpose prepass: emb[b][c][hw] -> g_delta[hw][c][b]
// ---------------------------------------------------------------------------
__global__ void prep_delta_kernel(const float* __restrict__ emb,
                                  const float* __restrict__ mean)
{
    __shared__ float s[8][32][33];
    const int hw0 = blockIdx.x * 32;
    const int c0  = blockIdx.y * 8;
    const int lane = threadIdx.x & 31;
    const int wrp  = threadIdx.x >> 5;

    const int c = c0 + wrp;
    const float m = mean[(size_t)c * HW + hw0 + lane];
    #pragma unroll 4
    for (int b = 0; b < B; b++) {
        float e = emb[((size_t)b * C + c) * HW + hw0 + lane];
        s[wrp][b][lane] = e - m;
    }
    __syncthreads();

    const int b  = threadIdx.x & 31;
    const int cl = threadIdx.x >> 5;
    #pragma unroll 4
    for (int hwl = 0; hwl < 32; hwl++) {
        g_delta[(size_t)(hw0 + hwl) * (C * B) + (c0 + cl) * B + b] = s[cl][b][hwl];
    }
}

// ---------------------------------------------------------------------------
// Kernel 2: per-pixel mahalanobis — PROVEN R8 VERSION (unchanged).
// 128 thr = 2 jg x 8 ty x 8 tx; 8 rows x 4 batches per thread, 32-col range.
// ---------------------------------------------------------------------------
__global__ void __launch_bounds__(128)
mahal_kernel(const float* __restrict__ invcov)
{
    extern __shared__ float sm[];
    float* Ds  = sm;
    float* Mb0 = sm + C * B;
    float* Mb1 = Mb0 + 64 * MSP2;

    const int p   = blockIdx.x;
    const int tid = threadIdx.x;
    const int tx  = tid & 7;
    const int g   = tid >> 3;
    const int ty  = g & 7;
    const int jg  = g >> 3;
    const int b0  = tx * 4;

    const float* Mp = invcov + (size_t)p * (C * C);

    const int   CI[6] = {0, 1, 1, 2, 2, 2};
    const int   CJ[6] = {0, 0, 1, 0, 1, 2};
    const float CW[6] = {1.f, 2.f, 1.f, 2.f, 2.f, 1.f};

    float4 st[8];
    #pragma unroll
    for (int o = 0; o < 8; o++) {
        int e4 = o * 128 + tid;
        int il = e4 >> 4;
        int jl = (e4 & 15) * 4;
        st[o] = *(const float4*)&Mp[(size_t)il * C + jl];
    }

    const float* dsrc = g_delta + (size_t)p * (C * B);
    #pragma unroll
    for (int i = tid * 4; i < C * B; i += 512)
        *(float4*)&Ds[i] = *(const float4*)&dsrc[i];

    #pragma unroll
    for (int i = tid * 4; i < 8 * C; i += 512)
        *(float4*)&Mb1[i] = *(const float4*)&Mp[(size_t)192 * C + i];

    __syncthreads();

    float q0 = 0.f, q1 = 0.f, q2 = 0.f, q3 = 0.f;

    #pragma unroll
    for (int rr = 0; rr < 8; rr++) {
        const float* mrow = &Mb1[rr * C];
        float p0 = 0.f, p1 = 0.f, p2 = 0.f, p3 = 0.f;
        #pragma unroll
        for (int s = 0; s < 12; s++) {
            int j = g + 16 * s;
            float wm = 2.f * mrow[j];
            float4 dj = *(const float4*)&Ds[j * B + b0];
            p0 += wm * dj.x; p1 += wm * dj.y;
            p2 += wm * dj.z; p3 += wm * dj.w;
        }
        if (g < 8) {
            int j = 192 + g;
            float wm = mrow[j];
            float4 dj = *(const float4*)&Ds[j * B + b0];
            p0 += wm * dj.x; p1 += wm * dj.y;
            p2 += wm * dj.z; p3 += wm * dj.w;
        }
        float4 di = *(const float4*)&Ds[(192 + rr) * B + b0];
        q0 += di.x * p0; q1 += di.y * p1; q2 += di.z * p2; q3 += di.w * p3;
    }

    #pragma unroll
    for (int k = 0; k < 6; k++) {
        float* buf = (k & 1) ? Mb1 : Mb0;
        __syncthreads();
        #pragma unroll
        for (int o = 0; o < 8; o++) {
            int e4 = o * 128 + tid;
            int il = e4 >> 4;
            int jl = (e4 & 15) * 4;
            *(float4*)&buf[il * MSP2 + jl] = st[o];
        }
        __syncthreads();

        if (k < 5) {
            const float* src = Mp + (size_t)(64 * CI[k + 1]) * C + 64 * CJ[k + 1];
            #pragma unroll
            for (int o = 0; o < 8; o++) {
                int e4 = o * 128 + tid;
                int il = e4 >> 4;
                int jl = (e4 & 15) * 4;
                st[o] = *(const float4*)&src[(size_t)il * C + jl];
            }
        }

        unsigned long long acc[8][2];
        #pragma unroll
        for (int r = 0; r < 8; r++) { acc[r][0] = 0ull; acc[r][1] = 0ull; }

        const float* dbase = &Ds[(64 * CJ[k] + jg * 32) * B + b0];
        const int mcol = jg * 32;
        #pragma unroll
        for (int u = 0; u < 8; u++) {
            float4 mv[8];
            #pragma unroll
            for (int r = 0; r < 8; r++)
                mv[r] = *(const float4*)&buf[(ty + 8 * r) * MSP2 + mcol + u * 4];
            #pragma unroll
            for (int jj = 0; jj < 4; jj++) {
                ulonglong2 du = *(const ulonglong2*)(dbase + (u * 4 + jj) * B);
                #pragma unroll
                for (int r = 0; r < 8; r++) {
                    float c = (jj == 0) ? mv[r].x : (jj == 1) ? mv[r].y
                            : (jj == 2) ? mv[r].z : mv[r].w;
                    unsigned long long m = pack2(c);
                    acc[r][0] = fma2(m, du.x, acc[r][0]);
                    acc[r][1] = fma2(m, du.y, acc[r][1]);
                }
            }
        }

        {
            const float w = CW[k];
            #pragma unroll
            for (int r = 0; r < 8; r++) {
                int i = 64 * CI[k] + ty + 8 * r;
                float4 dv = *(const float4*)&Ds[i * B + b0];
                float2 s0 = unpack2(acc[r][0]);
                float2 s1 = unpack2(acc[r][1]);
                q0 += w * dv.x * s0.x;
                q1 += w * dv.y * s0.y;
                q2 += w * dv.z * s1.x;
                q3 += w * dv.w * s1.y;
            }
        }
    }

    __syncthreads();
    float* red = Mb0;
    red[g * 33 + b0 + 0] = q0;
    red[g * 33 + b0 + 1] = q1;
    red[g * 33 + b0 + 2] = q2;
    red[g * 33 + b0 + 3] = q3;
    __syncthreads();
    if (tid < B) {
        float acc = 0.f;
        #pragma unroll
        for (int t = 0; t < 16; t++) acc += red[t * 33 + tid];
        g_dist[(size_t)tid * HW + p] = sqrtf(fmaxf(acc, 0.f));
    }
}

// ---------------------------------------------------------------------------
// Kernel 3: build combined operator K = G(blur, reflect-pad) * U(bilinear
// upsample, half-pixel, edge-clamp). K[y][s], y in [0,224), s in [0,56).
// One block, 224 threads (one output row each).
// ---------------------------------------------------------------------------
__global__ void kinit_kernel()
{
    __shared__ float g[KS];
    const int y = threadIdx.x;
    if (y < KS) {
        float x = (float)(y - 16);
        g[y] = expf(-(x * x) / 32.f);
    }
    __syncthreads();
    float gs = 0.f;
    #pragma unroll
    for (int i = 0; i < KS; i++) gs += g[i];
    const float inv = 1.f / gs;

    float acc[56];
    #pragma unroll
    for (int s = 0; s < 56; s++) acc[s] = 0.f;

    for (int k = 0; k < KS; k++) {
        int t = y + k - 16;
        if (t < 0) t = -t;
        if (t > OH - 1) t = 2 * (OH - 1) - t;
        float src = 0.25f * t - 0.375f;
        float fs = floorf(src);
        int s0 = (int)fs;
        float a = src - fs;
        int sa = min(max(s0, 0), 55);
        int sb = min(max(s0 + 1, 0), 55);
        float w = g[k] * inv;
        acc[sa] += w * (1.f - a);
        acc[sb] += w * a;
    }
    for (int s = 0; s < 56; s++) {
        g_K[y * 56 + s] = acc[s];
        g_KT[s * OH + y] = acc[s];
    }
}

// ---------------------------------------------------------------------------
// Kernel 4: pass1 (horizontal): tmp[b][y56][x] = sum_s K[x][s] * dist[b][y][s]
// grid = B*7 (8 y-rows per block), block 224.
// ---------------------------------------------------------------------------
__global__ void __launch_bounds__(224)
pass1_kernel()
{
    __shared__ float drow[8][56];
    const int b   = blockIdx.x / 7;
    const int yc0 = (blockIdx.x % 7) * 8;
    const int x   = threadIdx.x;

    for (int i = threadIdx.x; i < 8 * 56; i += 224)
        drow[i / 56][i % 56] = g_dist[(size_t)b * HW + (yc0 + i / 56) * 56 + (i % 56)];
    __syncthreads();

    float acc[8];
    #pragma unroll
    for (int r = 0; r < 8; r++) acc[r] = 0.f;

    #pragma unroll 4
    for (int s = 0; s < 56; s++) {
        float w = g_KT[s * OH + x];
        #pragma unroll
        for (int r = 0; r < 8; r++) acc[r] += w * drow[r][s];
    }
    #pragma unroll
    for (int r = 0; r < 8; r++)
        g_tmp[((size_t)b * 56 + yc0 + r) * OW + x] = acc[r];
}

// ---------------------------------------------------------------------------
// Kernel 5: pass2 (vertical): out[b][y][x] = sum_s K[y][s] * tmp[b][s][x]
// grid = B*8 (28 y-rows per block), block 224. tmp slab (56x224) in smem.
// ---------------------------------------------------------------------------
__global__ void __launch_bounds__(224)
pass2_kernel(float* __restrict__ out)
{
    extern __shared__ float p2[];
    float* slab = p2;              // 56*224 = 12544 floats
    float* Ks   = p2 + 56 * OW;    // 28*56  = 1568 floats

    const int b  = blockIdx.x >> 3;
    const int y0 = (blockIdx.x & 7) * 28;
    const int x  = threadIdx.x;

    const float* tsrc = g_tmp + (size_t)b * 56 * OW;
    for (int i = threadIdx.x; i < 56 * OW; i += 224) slab[i] = tsrc[i];
    for (int i = threadIdx.x; i < 28 * 56; i += 224)
        Ks[i] = g_K[(y0 + i / 56) * 56 + (i % 56)];
    __syncthreads();

    #pragma unroll 4
    for (int yy = 0; yy < 28; yy++) {
        float acc = 0.f;
        #pragma unroll 8
        for (int s = 0; s < 56; s++)
            acc += Ks[yy * 56 + s] * slab[s * OW + x];
        out[((size_t)b * OH + y0 + yy) * OW + x] = acc;
    }
}

// ---------------------------------------------------------------------------
// Launch
// ---------------------------------------------------------------------------
extern "C" void kernel_launch(void* const* d_in, const int* in_sizes, int n_in,
                              void* d_out, int out_size)
{
    const float* emb    = (const float*)d_in[0];
    const float* mean   = (const float*)d_in[1];
    const float* invcov = (const float*)d_in[2];
    float* out = (float*)d_out;

    const int mahal_smem = (C * B + 2 * 64 * MSP2) * (int)sizeof(float);  // 60416
    cudaFuncSetAttribute(mahal_kernel,
                         cudaFuncAttributeMaxDynamicSharedMemorySize, mahal_smem);
    const int p2_smem = (56 * OW + 28 * 56) * (int)sizeof(float);         // 56448
    cudaFuncSetAttribute(pass2_kernel,
                         cudaFuncAttributeMaxDynamicSharedMemorySize, p2_smem);

    kinit_kernel<<<1, 224>>>();

    dim3 prep_grid(HW / 32, C / 8);
    prep_delta_kernel<<<prep_grid, 256>>>(emb, mean);

    mahal_kernel<<<HW, 128, mahal_smem>>>(invcov);

    pass1_kernel<<<B * 7, 224>>>();
    pass2_kernel<<<B * 8, 224, p2_smem>>>(out);
}